// round 3
// baseline (speedup 1.0000x reference)
#include <cuda_runtime.h>
#include <math.h>

// ---------------------------------------------------------------------------
// YoloV1Loss — single fused kernel (last-block finalize).
//
// Per block (256 rows):
//   - stage aligned 64B chunk covering cols 0..9 of p,t (coalesced float4)
//   - per-row: noobj term / coord term (IoU argmax, lazy class gathers)
//   - emit: g_counts[b], g_noobj[b], g_csum[b], rank-compacted g_contrib
// Last block to finish:
//   - shfl-scan the 3136 counts -> n_obj, half
//   - sum csum for fully-taken blocks, partial (<=256 floats) for the single
//     boundary block, plus all noobj sums; write scalar; reset g_done.
// ---------------------------------------------------------------------------

#define RPB   256
#define MAXB  4096
#define NCLS  20
#define PAD   17

__device__ int      g_counts[MAXB];
__device__ float    g_noobj[MAXB];
__device__ float    g_csum[MAXB];
__device__ float    g_contrib[MAXB * RPB];
__device__ unsigned g_done;   // zero-initialized; finalizer resets it

__global__ void __launch_bounds__(RPB) yolo_fused(const float* __restrict__ p,
                                                  const float* __restrict__ t,
                                                  float* __restrict__ out,
                                                  int nrows) {
    __shared__ float ps[RPB * PAD];
    __shared__ float tsd[RPB * PAD];
    __shared__ int   wtot[RPB / 32];
    __shared__ float wredN[RPB / 32];
    __shared__ float wredC[RPB / 32];

    const int tid  = threadIdx.x;
    const int bid  = blockIdx.x;
    const int row0 = bid * RPB;
    const int lane = tid & 31;
    const int wid  = tid >> 5;

    // ---- stage aligned 64B chunks (floats [row*30 & ~7, +16)) ----
    for (int j = tid; j < RPB * 4; j += RPB) {
        const int r    = j >> 2;
        const int part = j & 3;
        const int gr   = row0 + r;
        if (gr < nrows) {
            const int chunkf = (gr * 30) & ~7;
            const float4 pv = *(const float4*)(p + chunkf + part * 4);
            const float4 tv = *(const float4*)(t + chunkf + part * 4);
            const int si = r * PAD + part * 4;
            ps[si + 0] = pv.x; ps[si + 1] = pv.y;
            ps[si + 2] = pv.z; ps[si + 3] = pv.w;
            tsd[si + 0] = tv.x; tsd[si + 1] = tv.y;
            tsd[si + 2] = tv.z; tsd[si + 3] = tv.w;
        }
    }
    __syncthreads();

    const int  grow    = row0 + tid;
    const bool inrange = (grow < nrows);
    const int  off     = (grow * 30) & 7;
    const float* pr = ps  + tid * PAD + off;   // pr[c] == p[grow*30+c], c<10
    const float* tr = tsd + tid * PAD + off;

    const float conf = inrange ? tr[4] : -1.0f;
    const bool  cm   = (conf == 1.0f);

    // ---- in-block inclusive rank of coord rows ----
    const unsigned bal = __ballot_sync(0xffffffffu, cm);
    unsigned le_mask;
    asm("mov.u32 %0, %%lanemask_le;" : "=r"(le_mask));
    const int inc = __popc(bal & le_mask);
    if (lane == 31) wtot[wid] = __popc(bal);
    __syncthreads();
    int woff = 0, ctot = 0;
#pragma unroll
    for (int i = 0; i < RPB / 32; i++) {
        const int c = wtot[i];
        if (i < wid) woff += c;
        ctot += c;
    }

    // ---- noobj term ----
    float nv = 0.0f;
    if (inrange && conf == 0.0f) {
        const float d0 = pr[4] - tr[4];
        const float d1 = pr[9] - tr[9];
        nv = 0.5f * (d0 * d0 + d1 * d1);
    }

    // ---- coord term (gate resolved by finalizer) ----
    float cv = 0.0f;
    if (cm) {
        const float C = 1.0f / 7.0f;
        const float tb0 = tr[0] * tr[0], tb1 = tr[1] * tr[1];
        const float tb2 = tr[2] * tr[2], tb3 = tr[3] * tr[3];
        const float tax = tb0 * C - tb2, tay = tb1 * C - tb3;
        const float tbx = tax * C + tb2, tby = tay * C + tb3;
        const float at  = (tbx - tax) * (tby - tay);

        float iou0 = 0.0f, iou1 = 0.0f;
#pragma unroll
        for (int b = 0; b < 2; b++) {
            const float x = pr[b * 5 + 0], y = pr[b * 5 + 1];
            const float w = pr[b * 5 + 2], h = pr[b * 5 + 3];
            const float ax = x * C - w,  ay = y * C - h;
            const float bx = ax * C + w, by = ay * C + h;
            const float iw = fmaxf(fminf(bx, tbx) - fmaxf(ax, tax), 0.0f);
            const float ih = fmaxf(fminf(by, tby) - fmaxf(ay, tay), 0.0f);
            const float inter = iw * ih;
            const float ap = (bx - ax) * (by - ay);
            const float iou = inter / (ap + at - inter);
            if (b == 0) iou0 = iou; else iou1 = iou;
        }
        int idx;
        if (isnan(iou0))      idx = 0;   // numpy argmax: NaN wins, first occ.
        else if (isnan(iou1)) idx = 1;
        else                  idx = (iou1 > iou0) ? 1 : 0;

        const int ob = idx * 5;
        const float s0 = pr[ob + 0] - tr[0];
        const float s1 = pr[ob + 1] - tr[1];
        const float s2 = pr[ob + 2] - tr[2];
        const float s3 = pr[ob + 3] - tr[3];

        // lazy class gather: t[grow,10:30] (10x float2), first-strict argmax
        const float* tg = t + grow * 30 + 10;
        float best = -1.0f;
        int   oi   = 0;
#pragma unroll
        for (int j = 0; j < NCLS / 2; j++) {
            const float2 v = *(const float2*)(tg + 2 * j);
            if (v.x > best) { best = v.x; oi = 2 * j; }
            if (v.y > best) { best = v.y; oi = 2 * j + 1; }
        }
        const float clv = __ldg(p + grow * 30 + 10 + oi) - 1.0f;

        cv = 5.0f * (s0 * s0 + s1 * s1 + s2 * s2 + s3 * s3 + 2.0f * clv * clv);
        g_contrib[bid * RPB + (woff + inc - 1)] = cv;
    }

    // ---- block reductions: noobj sum + coord sum ----
#pragma unroll
    for (int o = 16; o > 0; o >>= 1) {
        nv += __shfl_down_sync(0xffffffffu, nv, o);
        cv += __shfl_down_sync(0xffffffffu, cv, o);
    }
    if (lane == 0) { wredN[wid] = nv; wredC[wid] = cv; }
    __syncthreads();
    if (tid == 0) {
        float sn = 0.0f, sc = 0.0f;
#pragma unroll
        for (int i = 0; i < RPB / 32; i++) { sn += wredN[i]; sc += wredC[i]; }
        g_noobj[bid]  = sn;
        g_csum[bid]   = sc;
        g_counts[bid] = ctot;
    }

    // =================== last-block finalize ===================
    __threadfence();
    __shared__ bool amLast;
    if (tid == 0)
        amLast = (atomicAdd(&g_done, 1u) == gridDim.x - 1);
    __syncthreads();
    if (!amLast) return;
    __threadfence();   // make all blocks' results visible

    const int nb = gridDim.x;
    const int CH = (nb + RPB - 1) / RPB;     // counts per thread
    const int i0 = tid * CH;

    // per-thread chunk sum of counts
    int lsum = 0;
    for (int k = 0; k < CH; k++) {
        const int i = i0 + k;
        if (i < nb) lsum += g_counts[i];
    }
    // warp exclusive scan
    int incs = lsum;
#pragma unroll
    for (int o = 1; o < 32; o <<= 1) {
        const int v = __shfl_up_sync(0xffffffffu, incs, o);
        if (lane >= o) incs += v;
    }
    const int ex = incs - lsum;

    __shared__ int ws[RPB / 32];
    __shared__ int s_bb, s_take;
    if (tid == 0) { s_bb = -1; s_take = 0; }
    if (lane == 31) ws[wid] = incs;
    __syncthreads();
    int wbase = 0, total = 0;
#pragma unroll
    for (int i = 0; i < RPB / 32; i++) {
        const int v = ws[i];
        if (i < wid) wbase += v;
        total += v;
    }
    const int half = total >> 1;   // n_obj // 2

    // walk my chunk: full blocks via csum, find the single boundary block
    double acc = 0.0;
    int P = wbase + ex;
    for (int k = 0; k < CH; k++) {
        const int i = i0 + k;
        if (i < nb) {
            const int cnt  = g_counts[i];
            const int take = min(cnt, max(0, half - P));
            if (take == cnt)      acc += (double)g_csum[i];
            else if (take > 0)  { s_bb = i; s_take = take; }
            acc += (double)g_noobj[i];
            P += cnt;
        }
    }
    __syncthreads();

    // partial boundary block (<=256 floats)
    if (s_bb >= 0) {
        const float* cb = g_contrib + s_bb * RPB;
        for (int i = tid; i < s_take; i += RPB) acc += (double)cb[i];
    }

    // block reduce (double)
#pragma unroll
    for (int o = 16; o > 0; o >>= 1)
        acc += __shfl_down_sync(0xffffffffu, acc, o);
    __shared__ double sd[RPB / 32];
    if (lane == 0) sd[wid] = acc;
    __syncthreads();
    if (tid == 0) {
        double s = 0.0;
#pragma unroll
        for (int i = 0; i < RPB / 32; i++) s += sd[i];
        out[0] = (float)s;
        g_done = 0u;          // reset for next graph replay
    }
}

// ---------------------------------------------------------------------------
extern "C" void kernel_launch(void* const* d_in, const int* in_sizes, int n_in,
                              void* d_out, int out_size) {
    const float* p = (const float*)d_in[0];
    const float* t = (const float*)d_in[1];

    const int nrows   = in_sizes[0] / 30;
    const int nblocks = (nrows + RPB - 1) / RPB;

    yolo_fused<<<nblocks, RPB>>>(p, t, (float*)d_out, nrows);
}

// round 4
// speedup vs baseline: 1.0798x; 1.0798x over previous
#include <cuda_runtime.h>
#include <math.h>

// ---------------------------------------------------------------------------
// YoloV1Loss — register-streaming fused kernel.
// Key fact (R3 ncu): DRAM traffic is the FULL 192MB regardless of which cols
// we touch (128B line granularity vs 120B rows), so stream everything:
//   thread <- row pair (240B = 15 aligned float4 per array, 30 LDG.128 total)
//   all per-row math in registers (constant indices only; dynamic picks via
//   predicated selects), rank via dual ballots, last-block finalize.
// ---------------------------------------------------------------------------

#define TPB   128          // threads per block
#define RPB   256          // rows per block (2 per thread)
#define MAXB  4096
#define NCLS  20

__device__ int      g_counts[MAXB];
__device__ float    g_noobj[MAXB];
__device__ float    g_csum[MAXB];
__device__ float    g_contrib[MAXB * RPB];
__device__ unsigned g_done;          // zero-init; finalizer resets

// per-row loss terms; everything constant-indexed -> registers
__device__ __forceinline__ void row_terms(const float* tv, const float* pv,
                                          bool valid, bool& cm, float& nv,
                                          float& cv) {
    const float conf = valid ? tv[4] : -1.0f;
    cm = (conf == 1.0f);
    nv = 0.0f;
    cv = 0.0f;

    if (conf == 0.0f) {
        const float d0 = pv[4] - tv[4];
        const float d1 = pv[9] - tv[9];
        nv = 0.5f * (d0 * d0 + d1 * d1);
    }

    if (cm) {
        const float C = 1.0f / 7.0f;
        const float tb0 = tv[0] * tv[0], tb1 = tv[1] * tv[1];
        const float tb2 = tv[2] * tv[2], tb3 = tv[3] * tv[3];
        const float tax = tb0 * C - tb2, tay = tb1 * C - tb3;
        const float tbx = tax * C + tb2, tby = tay * C + tb3;
        const float at  = (tbx - tax) * (tby - tay);

        float iou[2];
#pragma unroll
        for (int b = 0; b < 2; b++) {
            const float x = pv[b * 5 + 0], y = pv[b * 5 + 1];
            const float w = pv[b * 5 + 2], h = pv[b * 5 + 3];
            const float ax = x * C - w,  ay = y * C - h;
            const float bx = ax * C + w, by = ay * C + h;
            const float iw = fmaxf(fminf(bx, tbx) - fmaxf(ax, tax), 0.0f);
            const float ih = fmaxf(fminf(by, tby) - fmaxf(ay, tay), 0.0f);
            const float inter = iw * ih;
            const float ap = (bx - ax) * (by - ay);
            iou[b] = inter / (ap + at - inter);
        }
        // numpy argmax (NaN is max, first occurrence wins)
        bool pick1;
        if (isnan(iou[0]))      pick1 = false;
        else if (isnan(iou[1])) pick1 = true;
        else                    pick1 = (iou[1] > iou[0]);

        const float s0 = (pick1 ? pv[5] : pv[0]) - tv[0];
        const float s1 = (pick1 ? pv[6] : pv[1]) - tv[1];
        const float s2 = (pick1 ? pv[7] : pv[2]) - tv[2];
        const float s3 = (pick1 ? pv[8] : pv[3]) - tv[3];

        // class argmax over tv[10..29] with paired p-select (no dyn index)
        float best = tv[10];
        float clp  = pv[10];
#pragma unroll
        for (int j = 1; j < NCLS; j++) {
            const float v = tv[10 + j];
            const bool  u = (v > best);
            best = u ? v : best;
            clp  = u ? pv[10 + j] : clp;
        }
        const float clv = clp - 1.0f;

        cv = 5.0f * (s0 * s0 + s1 * s1 + s2 * s2 + s3 * s3 + 2.0f * clv * clv);
    }
}

__global__ void __launch_bounds__(TPB)
yolo_fused(const float* __restrict__ p, const float* __restrict__ t,
           float* __restrict__ out, int nrows) {
    const int tid  = threadIdx.x;
    const int bid  = blockIdx.x;
    const int lane = tid & 31;
    const int wid  = tid >> 5;
    const int row0 = bid * RPB + 2 * tid;       // this thread's row pair
    const bool v0  = (row0 < nrows);
    const bool v1  = (row0 + 1 < nrows);

    // ---- stream the full row pair: 15 + 15 aligned float4 loads ----
    float tv[60], pv[60];
    if (v0) {
        const float4* tg = (const float4*)(t + (size_t)row0 * 30);
        const float4* pg = (const float4*)(p + (size_t)row0 * 30);
#pragma unroll
        for (int i = 0; i < 15; i++) ((float4*)tv)[i] = tg[i];
#pragma unroll
        for (int i = 0; i < 15; i++) ((float4*)pv)[i] = pg[i];
        if (!v1) { tv[34] = -1.0f; }            // poison row1 conf
    } else {
#pragma unroll
        for (int i = 0; i < 60; i++) { tv[i] = -1.0f; pv[i] = 0.0f; }
    }

    bool cm0, cm1;
    float nv0, cv0, nv1, cv1;
    row_terms(tv,      pv,      v0, cm0, nv0, cv0);
    row_terms(tv + 30, pv + 30, v1, cm1, nv1, cv1);

    // ---- block-inclusive rank of coord rows (row order: 2*tid, 2*tid+1) ----
    const unsigned bal0 = __ballot_sync(0xffffffffu, cm0);
    const unsigned bal1 = __ballot_sync(0xffffffffu, cm1);
    unsigned lt_mask;
    asm("mov.u32 %0, %%lanemask_lt;" : "=r"(lt_mask));
    const int before = __popc(bal0 & lt_mask) + __popc(bal1 & lt_mask);
    const int wcnt   = __popc(bal0) + __popc(bal1);

    __shared__ int   wtot[TPB / 32];
    __shared__ float wredN[TPB / 32];
    __shared__ float wredC[TPB / 32];
    if (lane == 0) wtot[wid] = wcnt;
    __syncthreads();
    int woff = 0, ctot = 0;
#pragma unroll
    for (int i = 0; i < TPB / 32; i++) {
        const int c = wtot[i];
        if (i < wid) woff += c;
        ctot += c;
    }

    const int r0 = woff + before + (cm0 ? 1 : 0);            // inclusive ranks
    const int r1 = r0 + (cm1 ? 1 : 0);
    if (cm0) g_contrib[bid * RPB + (r0 - 1)] = cv0;
    if (cm1) g_contrib[bid * RPB + (r1 - 1)] = cv1;

    // ---- block reductions ----
    float nv = nv0 + nv1;
    float cv = cv0 + cv1;
#pragma unroll
    for (int o = 16; o > 0; o >>= 1) {
        nv += __shfl_down_sync(0xffffffffu, nv, o);
        cv += __shfl_down_sync(0xffffffffu, cv, o);
    }
    if (lane == 0) { wredN[wid] = nv; wredC[wid] = cv; }
    __syncthreads();
    if (tid == 0) {
        float sn = 0.0f, sc = 0.0f;
#pragma unroll
        for (int i = 0; i < TPB / 32; i++) { sn += wredN[i]; sc += wredC[i]; }
        g_noobj[bid]  = sn;
        g_csum[bid]   = sc;
        g_counts[bid] = ctot;
    }

    // =================== last-block finalize ===================
    __threadfence();
    __shared__ bool amLast;
    if (tid == 0)
        amLast = (atomicAdd(&g_done, 1u) == gridDim.x - 1);
    __syncthreads();
    if (!amLast) return;
    __threadfence();

    const int nb = gridDim.x;
    const int CH = (nb + TPB - 1) / TPB;
    const int i0 = tid * CH;

    int lsum = 0;
    for (int k = 0; k < CH; k++) {
        const int i = i0 + k;
        if (i < nb) lsum += g_counts[i];
    }
    int incs = lsum;
#pragma unroll
    for (int o = 1; o < 32; o <<= 1) {
        const int x = __shfl_up_sync(0xffffffffu, incs, o);
        if (lane >= o) incs += x;
    }
    const int ex = incs - lsum;

    __shared__ int ws[TPB / 32];
    __shared__ int s_bb, s_take;
    if (tid == 0) { s_bb = -1; s_take = 0; }
    if (lane == 31) ws[wid] = incs;
    __syncthreads();
    int wbase = 0, total = 0;
#pragma unroll
    for (int i = 0; i < TPB / 32; i++) {
        const int x = ws[i];
        if (i < wid) wbase += x;
        total += x;
    }
    const int half = total >> 1;                 // n_obj // 2

    double acc = 0.0;
    int P = wbase + ex;
    for (int k = 0; k < CH; k++) {
        const int i = i0 + k;
        if (i < nb) {
            const int cnt  = g_counts[i];
            const int take = min(cnt, max(0, half - P));
            if (take == cnt)     acc += (double)g_csum[i];
            else if (take > 0) { s_bb = i; s_take = take; }
            acc += (double)g_noobj[i];
            P += cnt;
        }
    }
    __syncthreads();

    if (s_bb >= 0) {
        const float* cb = g_contrib + s_bb * RPB;
        for (int i = tid; i < s_take; i += TPB) acc += (double)cb[i];
    }

#pragma unroll
    for (int o = 16; o > 0; o >>= 1)
        acc += __shfl_down_sync(0xffffffffu, acc, o);
    __shared__ double sd[TPB / 32];
    if (lane == 0) sd[wid] = acc;
    __syncthreads();
    if (tid == 0) {
        double s = 0.0;
#pragma unroll
        for (int i = 0; i < TPB / 32; i++) s += sd[i];
        out[0] = (float)s;
        g_done = 0u;
    }
}

// ---------------------------------------------------------------------------
extern "C" void kernel_launch(void* const* d_in, const int* in_sizes, int n_in,
                              void* d_out, int out_size) {
    const float* p = (const float*)d_in[0];
    const float* t = (const float*)d_in[1];

    const int nrows   = in_sizes[0] / 30;
    const int nblocks = (nrows + RPB - 1) / RPB;

    yolo_fused<<<nblocks, TPB>>>(p, t, (float*)d_out, nrows);
}